// round 3
// baseline (speedup 1.0000x reference)
#include <cuda_runtime.h>
#include <cuda_bf16.h>

#define TT 512
#define BB 32
#define VV 8000
#define LL 100
#define SS (2*LL+1)   // 201
#define NEGF (-1e30f)

#define NSCAN BB      // 32 scan blocks (one per batch sample)
#define NPROD 384     // producer blocks
#define NBLK  (NSCAN + NPROD)

// Scratch (allocation-free rule: __device__ globals; zero-initialized at load)
__device__ float g_lp[TT*BB*SS];      // 13.2 MB
__device__ int   g_flags[TT*BB];      // row-ready flags (== epoch when ready)
__device__ int   g_epoch;

// 3-way logsumexp, MUFU-only fast path.
__device__ __forceinline__ float lse3(float a1, float a2, float a3) {
    float m = fmaxf(a1, fmaxf(a2, a3));
    float r = __expf(a1 - m) + __expf(a2 - m) + __expf(a3 - m);
    return m + __logf(r);
}

// ---------------------------------------------------------------------------
// K0: per-launch init (graph-replay safe: epoch increments, flags never reset)
// ---------------------------------------------------------------------------
__global__ void init_kernel(float* __restrict__ out) {
    g_epoch = g_epoch + 1;
    out[0] = 0.f;
}

// ---------------------------------------------------------------------------
// Fused kernel: blocks [0,32) run the alpha scan (consumer), blocks [32,416)
// stream log-softmax + gather (producer). All 416 blocks are co-resident.
// ---------------------------------------------------------------------------
__global__ __launch_bounds__(256) void fused_kernel(const float* __restrict__ acts,
                                                    const int* __restrict__ targets,
                                                    const int* __restrict__ act_lens,
                                                    const int* __restrict__ label_lens,
                                                    float* __restrict__ out) {
    const int epoch = g_epoch;
    const int tid = threadIdx.x;

    if (blockIdx.x >= NSCAN) {
        // ================= PRODUCER =================
        const int pid = blockIdx.x - NSCAN;
        __shared__ float sm[8], sv[8];
        __shared__ float sLogZ;

        for (int row = pid; row < TT*BB; row += NPROD) {
            const float* __restrict__ rowp = acts + (size_t)row * VV;
            const float4* __restrict__ p = (const float4*)rowp;

            float m = NEGF, s = 0.f;
            #pragma unroll 4
            for (int i = tid; i < VV/4; i += 256) {
                float4 v = p[i];
                float mx = fmaxf(fmaxf(v.x, v.y), fmaxf(v.z, v.w));
                if (mx > m) { s *= __expf(m - mx); m = mx; }
                s += __expf(v.x - m) + __expf(v.y - m) + __expf(v.z - m) + __expf(v.w - m);
            }
            #pragma unroll
            for (int off = 16; off; off >>= 1) {
                float m2 = __shfl_xor_sync(0xffffffffu, m, off);
                float s2 = __shfl_xor_sync(0xffffffffu, s, off);
                float M = fmaxf(m, m2);
                s = s * __expf(m - M) + s2 * __expf(m2 - M);
                m = M;
            }
            int w = tid >> 5;
            if ((tid & 31) == 0) { sm[w] = m; sv[w] = s; }
            __syncthreads();
            if (tid == 0) {
                float M = sm[0], Sv = sv[0];
                #pragma unroll
                for (int i = 1; i < 8; i++) {
                    float m2 = sm[i], s2 = sv[i];
                    float Mn = fmaxf(M, m2);
                    Sv = Sv * __expf(M - Mn) + s2 * __expf(m2 - Mn);
                    M = Mn;
                }
                sLogZ = M + __logf(Sv);
            }
            __syncthreads();

            // Gather the 201 extended-label emissions (row is L1-resident).
            if (tid < SS) {
                int b = row % BB;
                int lab = (tid & 1) ? __ldg(&targets[b*LL + (tid >> 1)]) : 0;
                g_lp[(size_t)row * SS + tid] = rowp[lab] - sLogZ;
            }
            __syncthreads();
            if (tid == 0) {
                __threadfence();                 // publish g_lp row
                g_flags[row] = epoch;            // release flag
                __threadfence();
            }
        }
    } else {
        // ================= SCAN (consumer) =================
        const int b = blockIdx.x;
        const int s = tid;                       // states 0..SS-1 live
        const int alen = act_lens[b];
        volatile int* vflags = g_flags;

        __shared__ float alpha[2][SS];

        bool cs = false;                         // can_skip for this state
        if (s < SS && (s & 1)) {
            int cur_lab = targets[b*LL + (s >> 1)];
            int prv_lab = (s >= 3) ? targets[b*LL + ((s - 2) >> 1)] : -1;
            cs = (cur_lab != 0) && (cur_lab != prv_lab);
        }

        // wait for rows t = 0..4 of this sample
        if (s == 0) {
            #pragma unroll
            for (int t = 0; t <= 4; t++)
                while (vflags[t*BB + b] != epoch) { }
            __threadfence();                     // acquire
        }
        __syncthreads();

        // init t = 0
        if (s < SS) {
            float a0 = NEGF;
            if (s <= 1) a0 = g_lp[(size_t)(0*BB + b)*SS + s];
            alpha[0][s] = a0;
        }

        // prefetch 4 time-steps of lp per thread
        float lpA[4], lpB[4];
        #pragma unroll
        for (int j = 0; j < 4; j++) {
            int t = 1 + j;
            lpA[j] = (s < SS) ? g_lp[(size_t)(t*BB + b)*SS + s] : 0.f;
        }
        __syncthreads();

        int cur = 1;                             // buffer parity for t
        for (int t0 = 1; t0 < TT; t0 += 4) {
            // wait + prefetch rows t0+4 .. t0+7
            if (s == 0) {
                #pragma unroll
                for (int j = 0; j < 4; j++) {
                    int tn = t0 + 4 + j;
                    if (tn < TT)
                        while (vflags[tn*BB + b] != epoch) { }
                }
                __threadfence();                 // acquire
            }
            __syncthreads();
            #pragma unroll
            for (int j = 0; j < 4; j++) {
                int tn = t0 + 4 + j;
                lpB[j] = (s < SS && tn < TT) ? g_lp[(size_t)(tn*BB + b)*SS + s] : 0.f;
            }
            #pragma unroll
            for (int j = 0; j < 4; j++) {
                int t = t0 + j;
                if (t >= TT) break;              // uniform across block
                int prv = cur ^ 1;
                if (s < SS) {
                    float a1 = alpha[prv][s];
                    float a2 = (s >= 1) ? alpha[prv][s - 1] : NEGF;
                    float a3 = (cs && s >= 2) ? alpha[prv][s - 2] : NEGF;
                    float nv = lse3(a1, a2, a3) + lpA[j];
                    alpha[cur][s] = (t < alen) ? nv : a1;
                }
                __syncthreads();
                cur ^= 1;
            }
            #pragma unroll
            for (int j = 0; j < 4; j++) lpA[j] = lpB[j];
        }

        if (s == 0) {
            int fin = cur ^ 1;                   // buffer holding alpha[T-1]
            int sl = 2 * label_lens[b];
            float a = alpha[fin][sl], c = alpha[fin][sl - 1];
            float m = fmaxf(a, c);
            float ll = m + __logf(__expf(a - m) + __expf(c - m));
            atomicAdd(out, -ll * (1.0f / (float)BB));
        }
    }
}

// ---------------------------------------------------------------------------
extern "C" void kernel_launch(void* const* d_in, const int* in_sizes, int n_in,
                              void* d_out, int out_size) {
    const float* acts       = (const float*)d_in[0];
    const int*   targets    = (const int*)d_in[1];
    const int*   act_lens   = (const int*)d_in[2];
    const int*   label_lens = (const int*)d_in[3];
    float* out = (float*)d_out;

    init_kernel<<<1, 1>>>(out);
    fused_kernel<<<NBLK, 256>>>(acts, targets, act_lens, label_lens, out);
}